// round 15
// baseline (speedup 1.0000x reference)
#include <cuda_runtime.h>
#include <math.h>

#define NUM_HEADS    32
#define HEAD_SIZE    128
#define NUM_KV_HEADS 8
#define GRP          4
#define BLK_SZ       16
#define MAX_BLOCKS   64
#define MAX_CTX      1024
#define NUM_SEQS     64
#define SCALE        0.08838834764831845f
#define LOG2E        1.4426950408889634f

#define PART         128                  // tokens per warp-partition
#define NPART        8                    // warps per CTA = partitions

__device__ __forceinline__ float4 ldcs4(const float* p) {
    return __ldcs((const float4*)p);
}

__global__ __launch_bounds__(256, 3)
void paged_attn(const float* __restrict__ q_in,
                const float* __restrict__ knew,
                const float* __restrict__ vnew,
                const float* __restrict__ kcache,
                const float* __restrict__ vcache,
                const int*   __restrict__ btab,
                const int*   __restrict__ ctxlen,
                float*       __restrict__ out)
{
    const int sh = blockIdx.x;           // s*8 + h
    const int s  = sh >> 3;
    const int h  = sh & 7;
    const int L  = ctxlen[s];
    const int np = (L + PART - 1) >> 7;  // active partitions, 1..8

    const int tid  = threadIdx.x;
    const int lane = tid & 31;
    const int w    = tid >> 5;           // warp = partition

    __shared__ float sh_q[GRP][HEAD_SIZE];            // 2 KB
    __shared__ float sh_p[NPART][GRP][PART];          // 16 KB
    __shared__ float sh_o[NPART][GRP][HEAD_SIZE];     // 16 KB
    __shared__ float sh_m[NPART][GRP], sh_s[NPART][GRP];
    __shared__ float sh_w[NPART][GRP];
    __shared__ int   sh_btab[MAX_BLOCKS];

    if (tid < MAX_BLOCKS) sh_btab[tid] = btab[s * MAX_BLOCKS + tid];
    for (int i = tid; i < GRP * HEAD_SIZE; i += 256) {
        int g = i >> 7, d = i & 127;
        sh_q[g][d] = q_in[(size_t)s * (NUM_HEADS * HEAD_SIZE) + (h * GRP + g) * HEAD_SIZE + d];
    }
    __syncthreads();

    const int t0 = w * PART;
    if (t0 < L) {
        const int n    = min(PART, L - t0);
        const int nblk = (n + BLK_SZ - 1) >> 4;      // 1..8
        const int npad = nblk << 4;
        const int tb   = lane & 15;
        const int half = lane >> 4;

        // ---- Phase A: scores, block by block (8-deep staged loads) ----
        #pragma unroll
        for (int b = 0; b < NPART; b++) {
            if (b < nblk) {
                const int pb = sh_btab[(w << 3) + b];
                const int t  = t0 + (b << 4) + tb;
                const int lt = (b << 4) + tb;

                const float* kb;
                int cs;
                if (t == L - 1) {
                    kb = knew + (size_t)s * (NUM_KV_HEADS * HEAD_SIZE) + h * HEAD_SIZE + half * 64;
                    cs = 8;
                } else {
                    kb = kcache + ((size_t)pb * NUM_KV_HEADS + h) * 2048 + (size_t)half * 1024 + tb * 8;
                    cs = 128;
                }

                float acc[GRP] = {0.f, 0.f, 0.f, 0.f};
                {   // pass A: first float4 of each j (8 staged loads)
                    float4 ka[8];
                    #pragma unroll
                    for (int jj = 0; jj < 8; jj++) ka[jj] = ldcs4(kb + jj * cs);
                    #pragma unroll
                    for (int jj = 0; jj < 8; jj++) {
                        const int d0 = half * 64 + jj * 8;
                        #pragma unroll
                        for (int g = 0; g < GRP; g++) {
                            float4 qa = *(const float4*)&sh_q[g][d0];
                            acc[g] += ka[jj].x * qa.x + ka[jj].y * qa.y
                                    + ka[jj].z * qa.z + ka[jj].w * qa.w;
                        }
                    }
                }
                {   // pass B: second float4 of each j
                    float4 kc[8];
                    #pragma unroll
                    for (int jj = 0; jj < 8; jj++) kc[jj] = ldcs4(kb + jj * cs + 4);
                    #pragma unroll
                    for (int jj = 0; jj < 8; jj++) {
                        const int d0 = half * 64 + jj * 8 + 4;
                        #pragma unroll
                        for (int g = 0; g < GRP; g++) {
                            float4 qa = *(const float4*)&sh_q[g][d0];
                            acc[g] += kc[jj].x * qa.x + kc[jj].y * qa.y
                                    + kc[jj].z * qa.z + kc[jj].w * qa.w;
                        }
                    }
                }
                #pragma unroll
                for (int g = 0; g < GRP; g++)
                    acc[g] += __shfl_xor_sync(0xffffffffu, acc[g], 16);
                if (half == 0) {
                    #pragma unroll
                    for (int g = 0; g < GRP; g++)
                        sh_p[w][g][lt] = (lt < n) ? acc[g] * SCALE : -1e30f;
                }
            } else {
                if (half == 0) {
                    const int lt = (b << 4) + tb;
                    #pragma unroll
                    for (int g = 0; g < GRP; g++) sh_p[w][g][lt] = 0.f;  // final prob 0
                }
            }
        }

        // ---- Phase B: warp-local softmax stats per head ----
        #pragma unroll
        for (int g = 0; g < GRP; g++) {
            float m = -1e30f;
            for (int i = lane; i < npad; i += 32) m = fmaxf(m, sh_p[w][g][i]);
            #pragma unroll
            for (int o = 16; o > 0; o >>= 1) m = fmaxf(m, __shfl_xor_sync(0xffffffffu, m, o));
            float sum = 0.f;
            for (int i = lane; i < npad; i += 32) {
                float e = exp2f((sh_p[w][g][i] - m) * LOG2E);
                sh_p[w][g][i] = e;
                sum += e;
            }
            #pragma unroll
            for (int o = 16; o > 0; o >>= 1) sum += __shfl_xor_sync(0xffffffffu, sum, o);
            if (lane == 0) { sh_m[w][g] = m; sh_s[w][g] = sum; }
        }

        // ---- Phase C: P@V. 16 d-iterations; each stages 8 block-loads ----
        {
            const int j  = lane & 3;
            const int dl = lane >> 2;                 // 0..7
            #pragma unroll
            for (int di = 0; di < 16; di++) {
                const int d = (di << 3) + dl;         // 0..127
                float4 vv[8];
                #pragma unroll
                for (int b = 0; b < NPART; b++) {
                    const int bc = min(b, nblk - 1);  // clamp: sh_p zero there
                    const float* vb = vcache
                        + ((size_t)sh_btab[(w << 3) + bc] * NUM_KV_HEADS + h) * 2048;
                    vv[b] = ldcs4(vb + d * 16 + j * 4);
                }
                const float vnd = vnew[(size_t)s * (NUM_KV_HEADS * HEAD_SIZE) + h * HEAD_SIZE + d];
                float acc[GRP] = {0.f, 0.f, 0.f, 0.f};
                #pragma unroll
                for (int b = 0; b < NPART; b++) {
                    const int ltj = (b << 4) + (j << 2);
                    const int o = (L - 1) - (t0 + ltj);   // new-token value override
                    if ((unsigned)o < 4u) {
                        if      (o == 0) vv[b].x = vnd;
                        else if (o == 1) vv[b].y = vnd;
                        else if (o == 2) vv[b].z = vnd;
                        else             vv[b].w = vnd;
                    }
                    #pragma unroll
                    for (int g = 0; g < GRP; g++) {
                        float4 pr = *(const float4*)&sh_p[w][g][ltj];
                        acc[g] += vv[b].x * pr.x + vv[b].y * pr.y
                                + vv[b].z * pr.z + vv[b].w * pr.w;
                    }
                }
                #pragma unroll
                for (int g = 0; g < GRP; g++) {
                    acc[g] += __shfl_xor_sync(0xffffffffu, acc[g], 1);
                    acc[g] += __shfl_xor_sync(0xffffffffu, acc[g], 2);
                }
                if (j == 0) {
                    #pragma unroll
                    for (int g = 0; g < GRP; g++) sh_o[w][g][d] = acc[g];
                }
            }
        }
    }
    __syncthreads();

    // ---- intra-CTA combine: weights from smem (one warp) ----
    if (w == 0) {
        const int g  = lane & 3;
        const int pp = lane >> 2;                    // 0..7
        const bool act = (pp < np);
        float m = act ? sh_m[pp][g] : -1e30f;
        float M = m;
        #pragma unroll
        for (int o = 4; o < 32; o <<= 1) M = fmaxf(M, __shfl_xor_sync(0xffffffffu, M, o));
        float wv  = act ? exp2f((m - M) * LOG2E) : 0.f;
        float den = act ? wv * sh_s[pp][g] : 0.f;
        #pragma unroll
        for (int o = 4; o < 32; o <<= 1) den += __shfl_xor_sync(0xffffffffu, den, o);
        sh_w[pp][g] = wv / den;
    }
    __syncthreads();

    for (int i = tid; i < GRP * HEAD_SIZE; i += 256) {
        const int g = i >> 7, d = i & 127;
        float acc = 0.f;
        for (int pp = 0; pp < np; pp++)
            acc += sh_w[pp][g] * sh_o[pp][g][d];
        out[(size_t)s * (NUM_HEADS * HEAD_SIZE) + (h * GRP + g) * HEAD_SIZE + d] = acc;
    }
}

extern "C" void kernel_launch(void* const* d_in, const int* in_sizes, int n_in,
                              void* d_out, int out_size)
{
    const float* query       = (const float*)d_in[0];
    const float* key         = (const float*)d_in[1];
    const float* value       = (const float*)d_in[2];
    const float* key_cache   = (const float*)d_in[3];
    const float* value_cache = (const float*)d_in[4];
    const int*   block_tab   = (const int*)d_in[5];
    const int*   ctx_lens    = (const int*)d_in[6];
    float* out = (float*)d_out;

    paged_attn<<<NUM_SEQS * NUM_KV_HEADS, 256>>>(
        query, key, value, key_cache, value_cache, block_tab, ctx_lens, out);
}

// round 16
// speedup vs baseline: 1.7695x; 1.7695x over previous
#include <cuda_runtime.h>
#include <math.h>

#define NUM_HEADS    32
#define HEAD_SIZE    128
#define NUM_KV_HEADS 8
#define GRP          4
#define BLK_SZ       16
#define MAX_BLOCKS   64
#define MAX_CTX      1024
#define NUM_SEQS     64
#define SCALE        0.08838834764831845f
#define LOG2E        1.4426950408889634f

#define PART         128                  // tokens per split-K partition
#define MAXP         (MAX_CTX / PART)     // 8
#define PBLK         (PART / BLK_SZ)      // 8 blocks per partition

// split-K scratch (device globals: no allocation allowed)
__device__ float g_po[NUM_SEQS * NUM_KV_HEADS * MAXP * GRP * HEAD_SIZE]; // 8 MB
__device__ float g_pm[NUM_SEQS * NUM_KV_HEADS * MAXP * GRP];
__device__ float g_ps[NUM_SEQS * NUM_KV_HEADS * MAXP * GRP];
__device__ int   g_cnt[NUM_SEQS * NUM_KV_HEADS];   // zero-init; self-resetting

__device__ __forceinline__ float4 ldcs4(const float* p) {
    return __ldcs((const float4*)p);
}

__global__ __launch_bounds__(256, 3)
void paged_attn_split(const float* __restrict__ q_in,
                      const float* __restrict__ knew,
                      const float* __restrict__ vnew,
                      const float* __restrict__ kcache,
                      const float* __restrict__ vcache,
                      const int*   __restrict__ btab,
                      const int*   __restrict__ ctxlen,
                      float*       __restrict__ out)
{
    const int bx = blockIdx.x;
    const int s  = bx >> 6;              // sequence
    const int h  = (bx >> 3) & 7;        // kv head
    const int p  = bx & 7;               // partition
    const int sh = (s << 3) | h;

    const int L  = ctxlen[s];
    const int t0 = p * PART;
    if (t0 >= L) return;
    const int np   = (L + PART - 1) / PART;
    const int t1   = min(L, t0 + PART);
    const int n    = t1 - t0;
    const int nblk = (n + BLK_SZ - 1) / BLK_SZ;     // 1..8
    const int npad = nblk * BLK_SZ;

    const int tid  = threadIdx.x;
    const int lane = tid & 31;
    const int wid  = tid >> 5;

    __shared__ float sh_q[GRP][HEAD_SIZE];       // 2 KB
    __shared__ float sh_p[GRP][PART];            // 2 KB
    __shared__ float sh_acc[GRP][HEAD_SIZE];     // 2 KB
    __shared__ float sh_m[GRP], sh_s[GRP];
    __shared__ float sh_w[MAXP][GRP];
    __shared__ int   sh_btab[PBLK];
    __shared__ int   sh_win;

    if (tid < PBLK) sh_btab[tid] = btab[s * MAX_BLOCKS + p * PBLK + tid];
    if (tid < 128) {   // q: 512 floats as 128 float4
        ((float4*)&sh_q[0][0])[tid] =
            *(const float4*)(q_in + (size_t)s * (NUM_HEADS * HEAD_SIZE)
                                   + h * GRP * HEAD_SIZE + tid * 4);
    }
    __syncthreads();

    // ---- Phase 1: warp per 16-token block; fully-coalesced chunk mapping.
    //      lane = tb*2 + xh: per chunk the warp loads one contiguous 512B run.
    if (wid < nblk) {
        const int tb = lane >> 1;            // token 0..15
        const int xh = lane & 1;             // x-half (dims xh*4..xh*4+3 of chunk)
        const int pb = sh_btab[wid];
        const int t  = t0 + wid * BLK_SZ + tb;
        const int lt = wid * BLK_SZ + tb;

        const float* kb;
        int cs;                               // chunk stride (floats)
        if (t == L - 1) {
            kb = knew + (size_t)s * (NUM_KV_HEADS * HEAD_SIZE) + h * HEAD_SIZE + xh * 4;
            cs = 8;
        } else {
            kb = kcache + ((size_t)pb * NUM_KV_HEADS + h) * 2048 + tb * 8 + xh * 4;
            cs = 128;
        }

        float acc[GRP] = {0.f, 0.f, 0.f, 0.f};

        {   // pass A: chunks 0..7 (8 staged, fully coalesced LDG.128)
            float4 ka[8];
            #pragma unroll
            for (int c = 0; c < 8; c++) ka[c] = ldcs4(kb + c * cs);
            #pragma unroll
            for (int c = 0; c < 8; c++) {
                const int d0 = c * 8 + xh * 4;
                #pragma unroll
                for (int g = 0; g < GRP; g++) {
                    float4 qa = *(const float4*)&sh_q[g][d0];
                    acc[g] += ka[c].x * qa.x + ka[c].y * qa.y
                            + ka[c].z * qa.z + ka[c].w * qa.w;
                }
            }
        }
        {   // pass B: chunks 8..15
            float4 kc[8];
            #pragma unroll
            for (int c = 0; c < 8; c++) kc[c] = ldcs4(kb + (c + 8) * cs);
            #pragma unroll
            for (int c = 0; c < 8; c++) {
                const int d0 = (c + 8) * 8 + xh * 4;
                #pragma unroll
                for (int g = 0; g < GRP; g++) {
                    float4 qa = *(const float4*)&sh_q[g][d0];
                    acc[g] += kc[c].x * qa.x + kc[c].y * qa.y
                            + kc[c].z * qa.z + kc[c].w * qa.w;
                }
            }
        }

        // combine the two x-halves (lane pairs)
        #pragma unroll
        for (int g = 0; g < GRP; g++)
            acc[g] += __shfl_xor_sync(0xffffffffu, acc[g], 1);

        if (xh == 0) {
            #pragma unroll
            for (int g = 0; g < GRP; g++)
                sh_p[g][lt] = (lt < n) ? acc[g] * SCALE : -1e30f;
        }
    } else {
        // zero-pad probabilities for inactive blocks (phase 3 runs fixed 8 blocks)
        if ((lane & 1) == 0) {
            const int lt = wid * BLK_SZ + (lane >> 1);
            #pragma unroll
            for (int g = 0; g < GRP; g++) sh_p[g][lt] = 0.f;
        }
    }
    __syncthreads();

    // ---- Phase 2: local softmax stats (4 warps, one head each) ----
    if (wid < GRP) {
        const int g = wid;
        float m = -1e30f;
        for (int i = lane; i < npad; i += 32) m = fmaxf(m, sh_p[g][i]);
        #pragma unroll
        for (int o = 16; o > 0; o >>= 1) m = fmaxf(m, __shfl_xor_sync(0xffffffffu, m, o));
        float sum = 0.f;
        for (int i = lane; i < npad; i += 32) {
            float e = exp2f((sh_p[g][i] - m) * LOG2E);
            sh_p[g][i] = e;
            sum += e;
        }
        #pragma unroll
        for (int o = 16; o > 0; o >>= 1) sum += __shfl_xor_sync(0xffffffffu, sum, o);
        if (lane == 0) { sh_m[g] = m; sh_s[g] = sum; }
    }
    __syncthreads();

    // ---- Phase 3: partial P@V, coalesced; two passes of 4 blocks (8 staged) ----
    {
        const int j  = lane & 3;
        const int d0 = (wid << 3) + (lane >> 2);     // 0..63
        const int d1 = d0 + 64;
        const float vnd0 = vnew[(size_t)s * (NUM_KV_HEADS * HEAD_SIZE) + h * HEAD_SIZE + d0];
        const float vnd1 = vnew[(size_t)s * (NUM_KV_HEADS * HEAD_SIZE) + h * HEAD_SIZE + d1];

        float acc0[GRP] = {0.f, 0.f, 0.f, 0.f};
        float acc1[GRP] = {0.f, 0.f, 0.f, 0.f};

        #pragma unroll
        for (int bp = 0; bp < 2; bp++) {
            float4 v0[4], v1[4];
            #pragma unroll
            for (int bb = 0; bb < 4; bb++) {
                const int b  = bp * 4 + bb;
                const int bc = min(b, nblk - 1);      // clamp: sh_p is zero there
                const float* vb = vcache + ((size_t)sh_btab[bc] * NUM_KV_HEADS + h) * 2048;
                v0[bb] = ldcs4(vb + d0 * 16 + j * 4);
                v1[bb] = ldcs4(vb + d1 * 16 + j * 4);
            }
            #pragma unroll
            for (int bb = 0; bb < 4; bb++) {
                const int b   = bp * 4 + bb;
                const int ltj = b * BLK_SZ + j * 4;
                const int o = (L - 1) - (t0 + ltj);   // new-token value override
                if ((unsigned)o < 4u) {
                    if      (o == 0) { v0[bb].x = vnd0; v1[bb].x = vnd1; }
                    else if (o == 1) { v0[bb].y = vnd0; v1[bb].y = vnd1; }
                    else if (o == 2) { v0[bb].z = vnd0; v1[bb].z = vnd1; }
                    else             { v0[bb].w = vnd0; v1[bb].w = vnd1; }
                }
                #pragma unroll
                for (int g = 0; g < GRP; g++) {
                    float4 pr = *(const float4*)&sh_p[g][ltj];
                    acc0[g] += v0[bb].x * pr.x + v0[bb].y * pr.y + v0[bb].z * pr.z + v0[bb].w * pr.w;
                    acc1[g] += v1[bb].x * pr.x + v1[bb].y * pr.y + v1[bb].z * pr.z + v1[bb].w * pr.w;
                }
            }
        }
        // reduce over token quads (lane bits 0-1)
        #pragma unroll
        for (int g = 0; g < GRP; g++) {
            acc0[g] += __shfl_xor_sync(0xffffffffu, acc0[g], 1);
            acc0[g] += __shfl_xor_sync(0xffffffffu, acc0[g], 2);
            acc1[g] += __shfl_xor_sync(0xffffffffu, acc1[g], 1);
            acc1[g] += __shfl_xor_sync(0xffffffffu, acc1[g], 2);
        }
        if (j == 0) {
            #pragma unroll
            for (int g = 0; g < GRP; g++) {
                sh_acc[g][d0] = acc0[g];
                sh_acc[g][d1] = acc1[g];
            }
        }
    }
    __syncthreads();

    // ---- write partials (vectorized: 128 float4) ----
    const size_t base4 = ((size_t)bx) * (GRP * HEAD_SIZE / 4);
    if (tid < 128)
        ((float4*)g_po)[base4 + tid] = ((const float4*)&sh_acc[0][0])[tid];
    if (tid < GRP) {
        g_pm[(size_t)bx * GRP + tid] = sh_m[tid];
        g_ps[(size_t)bx * GRP + tid] = sh_s[tid];
    }

    // ---- fused combine: last CTA for (s,h) finalizes ----
    __threadfence();
    if (tid == 0) {
        int old = atomicAdd(&g_cnt[sh], 1);
        sh_win = (old == np - 1);
        if (sh_win) g_cnt[sh] = 0;   // self-reset for graph replay
    }
    __syncthreads();
    if (!sh_win) return;
    __threadfence();                  // acquire: see all partitions' partials

    // one warp computes combine weights: lane = g + 4*pp
    if (wid == 0) {
        const int g  = lane & 3;
        const int pp = lane >> 2;
        const bool act = (pp < np);
        const size_t idx = ((size_t)sh * MAXP + pp) * GRP + g;
        float m  = act ? g_pm[idx] : -1e30f;
        float M = m;
        #pragma unroll
        for (int o = 4; o < 32; o <<= 1) M = fmaxf(M, __shfl_xor_sync(0xffffffffu, M, o));
        float w  = act ? exp2f((m - M) * LOG2E) : 0.f;
        float den = act ? w * g_ps[idx] : 0.f;
        #pragma unroll
        for (int o = 4; o < 32; o <<= 1) den += __shfl_xor_sync(0xffffffffu, den, o);
        sh_w[pp][g] = w / den;
    }
    __syncthreads();

    // ---- final output (vectorized: 128 float4) ----
    if (tid < 128) {
        const int g = tid >> 5;                      // 32 float4 per head
        float4 acc = make_float4(0.f, 0.f, 0.f, 0.f);
        for (int pp = 0; pp < np; pp++) {
            const float wv = sh_w[pp][g];
            float4 v = ((const float4*)g_po)[((size_t)sh * MAXP + pp) * 128 + tid];
            acc.x += wv * v.x; acc.y += wv * v.y;
            acc.z += wv * v.z; acc.w += wv * v.w;
        }
        ((float4*)out)[(size_t)s * (NUM_HEADS * HEAD_SIZE / 4)
                       + h * (GRP * HEAD_SIZE / 4) + tid] = acc;
    }
}

extern "C" void kernel_launch(void* const* d_in, const int* in_sizes, int n_in,
                              void* d_out, int out_size)
{
    const float* query       = (const float*)d_in[0];
    const float* key         = (const float*)d_in[1];
    const float* value       = (const float*)d_in[2];
    const float* key_cache   = (const float*)d_in[3];
    const float* value_cache = (const float*)d_in[4];
    const int*   block_tab   = (const int*)d_in[5];
    const int*   ctx_lens    = (const int*)d_in[6];
    float* out = (float*)d_out;

    paged_attn_split<<<NUM_SEQS * NUM_KV_HEADS * MAXP, 256>>>(
        query, key, value, key_cache, value_cache, block_tab, ctx_lens, out);
}

// round 17
// speedup vs baseline: 1.8585x; 1.0503x over previous
#include <cuda_runtime.h>
#include <math.h>

#define NUM_HEADS    32
#define HEAD_SIZE    128
#define NUM_KV_HEADS 8
#define GRP          4
#define BLK_SZ       16
#define MAX_BLOCKS   64
#define MAX_CTX      1024
#define NUM_SEQS     64
#define SCALE        0.08838834764831845f
#define LOG2E        1.4426950408889634f

#define PART         256                  // tokens per split-K partition
#define MAXP         (MAX_CTX / PART)     // 4
#define PBLK         (PART / BLK_SZ)      // 16 blocks per partition

// split-K scratch (device globals: no allocation allowed)
__device__ float g_po[NUM_SEQS * NUM_KV_HEADS * MAXP * GRP * HEAD_SIZE]; // 4 MB
__device__ float g_pm[NUM_SEQS * NUM_KV_HEADS * MAXP * GRP];
__device__ float g_ps[NUM_SEQS * NUM_KV_HEADS * MAXP * GRP];
__device__ int   g_cnt[NUM_SEQS * NUM_KV_HEADS];   // zero-init; self-resetting

__device__ __forceinline__ float4 ldcs4(const float* p) {
    return __ldcs((const float4*)p);
}

__global__ __launch_bounds__(256, 3)
void paged_attn_split(const float* __restrict__ q_in,
                      const float* __restrict__ knew,
                      const float* __restrict__ vnew,
                      const float* __restrict__ kcache,
                      const float* __restrict__ vcache,
                      const int*   __restrict__ btab,
                      const int*   __restrict__ ctxlen,
                      float*       __restrict__ out)
{
    const int bx = blockIdx.x;
    const int s  = bx >> 5;              // sequence
    const int h  = (bx >> 2) & 7;        // kv head
    const int p  = bx & 3;               // partition
    const int sh = (s << 3) | h;

    const int L  = ctxlen[s];
    const int t0 = p * PART;
    if (t0 >= L) return;
    const int np   = (L + PART - 1) / PART;         // 1..4
    const int t1   = min(L, t0 + PART);
    const int n    = t1 - t0;
    const int nblk = (n + BLK_SZ - 1) / BLK_SZ;     // 1..16
    const int npad = nblk * BLK_SZ;

    const int tid  = threadIdx.x;
    const int lane = tid & 31;
    const int wid  = tid >> 5;

    __shared__ float sh_q[GRP][HEAD_SIZE];       // 2 KB
    __shared__ float sh_p[GRP][PART];            // 4 KB
    __shared__ float sh_acc[GRP][HEAD_SIZE];     // 2 KB
    __shared__ float sh_m[GRP], sh_s[GRP];
    __shared__ float sh_w[MAXP][GRP];
    __shared__ int   sh_btab[PBLK];
    __shared__ int   sh_win;

    if (tid < PBLK) sh_btab[tid] = btab[s * MAX_BLOCKS + p * PBLK + tid];
    if (tid < 128) {   // q: 512 floats as 128 float4
        ((float4*)&sh_q[0][0])[tid] =
            *(const float4*)(q_in + (size_t)s * (NUM_HEADS * HEAD_SIZE)
                                   + h * GRP * HEAD_SIZE + tid * 4);
    }
    __syncthreads();

    // ---- Phase 1: warp scores blocks wid and wid+8; coalesced chunk mapping.
    //      lane = tb*2 + xh: per chunk the warp loads one contiguous 512B run.
    {
        const int tb = lane >> 1;            // token 0..15
        const int xh = lane & 1;             // x-half (dims xh*4..xh*4+3 of chunk)

        #pragma unroll
        for (int bb = 0; bb < 2; bb++) {
            const int b = wid + bb * 8;      // block 0..15
            if (b < nblk) {
                const int pb = sh_btab[b];
                const int t  = t0 + b * BLK_SZ + tb;
                const int lt = b * BLK_SZ + tb;

                const float* kb;
                int cs;                      // chunk stride (floats)
                if (t == L - 1) {
                    kb = knew + (size_t)s * (NUM_KV_HEADS * HEAD_SIZE) + h * HEAD_SIZE + xh * 4;
                    cs = 8;
                } else {
                    kb = kcache + ((size_t)pb * NUM_KV_HEADS + h) * 2048 + tb * 8 + xh * 4;
                    cs = 128;
                }

                float acc[GRP] = {0.f, 0.f, 0.f, 0.f};
                {   // pass A: chunks 0..7 (8 staged, fully coalesced LDG.128)
                    float4 ka[8];
                    #pragma unroll
                    for (int c = 0; c < 8; c++) ka[c] = ldcs4(kb + c * cs);
                    #pragma unroll
                    for (int c = 0; c < 8; c++) {
                        const int d0 = c * 8 + xh * 4;
                        #pragma unroll
                        for (int g = 0; g < GRP; g++) {
                            float4 qa = *(const float4*)&sh_q[g][d0];
                            acc[g] += ka[c].x * qa.x + ka[c].y * qa.y
                                    + ka[c].z * qa.z + ka[c].w * qa.w;
                        }
                    }
                }
                {   // pass B: chunks 8..15
                    float4 kc[8];
                    #pragma unroll
                    for (int c = 0; c < 8; c++) kc[c] = ldcs4(kb + (c + 8) * cs);
                    #pragma unroll
                    for (int c = 0; c < 8; c++) {
                        const int d0 = (c + 8) * 8 + xh * 4;
                        #pragma unroll
                        for (int g = 0; g < GRP; g++) {
                            float4 qa = *(const float4*)&sh_q[g][d0];
                            acc[g] += kc[c].x * qa.x + kc[c].y * qa.y
                                    + kc[c].z * qa.z + kc[c].w * qa.w;
                        }
                    }
                }
                #pragma unroll
                for (int g = 0; g < GRP; g++)
                    acc[g] += __shfl_xor_sync(0xffffffffu, acc[g], 1);
                if (xh == 0) {
                    #pragma unroll
                    for (int g = 0; g < GRP; g++)
                        sh_p[g][lt] = (lt < n) ? acc[g] * SCALE : -1e30f;
                }
            } else {
                // zero-pad probabilities for inactive blocks
                if (xh == 0) {
                    const int lt = b * BLK_SZ + tb;
                    #pragma unroll
                    for (int g = 0; g < GRP; g++) sh_p[g][lt] = 0.f;
                }
            }
        }
    }
    __syncthreads();

    // ---- Phase 2: local softmax stats (4 warps, one head each) ----
    if (wid < GRP) {
        const int g = wid;
        float m = -1e30f;
        for (int i = lane; i < npad; i += 32) m = fmaxf(m, sh_p[g][i]);
        #pragma unroll
        for (int o = 16; o > 0; o >>= 1) m = fmaxf(m, __shfl_xor_sync(0xffffffffu, m, o));
        float sum = 0.f;
        for (int i = lane; i < npad; i += 32) {
            float e = exp2f((sh_p[g][i] - m) * LOG2E);
            sh_p[g][i] = e;
            sum += e;
        }
        #pragma unroll
        for (int o = 16; o > 0; o >>= 1) sum += __shfl_xor_sync(0xffffffffu, sum, o);
        if (lane == 0) { sh_m[g] = m; sh_s[g] = sum; }
    }
    __syncthreads();

    // ---- Phase 3: partial P@V, coalesced; four passes of 4 blocks (8 staged) ----
    {
        const int j  = lane & 3;
        const int d0 = (wid << 3) + (lane >> 2);     // 0..63
        const int d1 = d0 + 64;
        const float vnd0 = vnew[(size_t)s * (NUM_KV_HEADS * HEAD_SIZE) + h * HEAD_SIZE + d0];
        const float vnd1 = vnew[(size_t)s * (NUM_KV_HEADS * HEAD_SIZE) + h * HEAD_SIZE + d1];

        float acc0[GRP] = {0.f, 0.f, 0.f, 0.f};
        float acc1[GRP] = {0.f, 0.f, 0.f, 0.f};

        #pragma unroll
        for (int bp = 0; bp < 4; bp++) {
            float4 v0[4], v1[4];
            #pragma unroll
            for (int bb = 0; bb < 4; bb++) {
                const int b  = bp * 4 + bb;
                const int bc = min(b, nblk - 1);      // clamp: sh_p is zero there
                const float* vb = vcache + ((size_t)sh_btab[bc] * NUM_KV_HEADS + h) * 2048;
                v0[bb] = ldcs4(vb + d0 * 16 + j * 4);
                v1[bb] = ldcs4(vb + d1 * 16 + j * 4);
            }
            #pragma unroll
            for (int bb = 0; bb < 4; bb++) {
                const int b   = bp * 4 + bb;
                const int ltj = b * BLK_SZ + j * 4;
                const int o = (L - 1) - (t0 + ltj);   // new-token value override
                if ((unsigned)o < 4u) {
                    if      (o == 0) { v0[bb].x = vnd0; v1[bb].x = vnd1; }
                    else if (o == 1) { v0[bb].y = vnd0; v1[bb].y = vnd1; }
                    else if (o == 2) { v0[bb].z = vnd0; v1[bb].z = vnd1; }
                    else             { v0[bb].w = vnd0; v1[bb].w = vnd1; }
                }
                #pragma unroll
                for (int g = 0; g < GRP; g++) {
                    float4 pr = *(const float4*)&sh_p[g][ltj];
                    acc0[g] += v0[bb].x * pr.x + v0[bb].y * pr.y + v0[bb].z * pr.z + v0[bb].w * pr.w;
                    acc1[g] += v1[bb].x * pr.x + v1[bb].y * pr.y + v1[bb].z * pr.z + v1[bb].w * pr.w;
                }
            }
        }
        // reduce over token quads (lane bits 0-1)
        #pragma unroll
        for (int g = 0; g < GRP; g++) {
            acc0[g] += __shfl_xor_sync(0xffffffffu, acc0[g], 1);
            acc0[g] += __shfl_xor_sync(0xffffffffu, acc0[g], 2);
            acc1[g] += __shfl_xor_sync(0xffffffffu, acc1[g], 1);
            acc1[g] += __shfl_xor_sync(0xffffffffu, acc1[g], 2);
        }
        if (j == 0) {
            #pragma unroll
            for (int g = 0; g < GRP; g++) {
                sh_acc[g][d0] = acc0[g];
                sh_acc[g][d1] = acc1[g];
            }
        }
    }
    __syncthreads();

    // ---- write partials (vectorized: 128 float4) ----
    const size_t base4 = ((size_t)bx) * (GRP * HEAD_SIZE / 4);
    if (tid < 128)
        ((float4*)g_po)[base4 + tid] = ((const float4*)&sh_acc[0][0])[tid];
    if (tid < GRP) {
        g_pm[(size_t)bx * GRP + tid] = sh_m[tid];
        g_ps[(size_t)bx * GRP + tid] = sh_s[tid];
    }

    // ---- fused combine: last CTA for (s,h) finalizes ----
    __threadfence();
    if (tid == 0) {
        int old = atomicAdd(&g_cnt[sh], 1);
        sh_win = (old == np - 1);
        if (sh_win) g_cnt[sh] = 0;   // self-reset for graph replay
    }
    __syncthreads();
    if (!sh_win) return;
    __threadfence();                  // acquire: see all partitions' partials

    // one warp computes combine weights: lane = g + 4*pp (pp < MAXP=4 active)
    if (wid == 0) {
        const int g  = lane & 3;
        const int pp = lane >> 2;
        const bool act = (pp < np);
        const size_t idx = ((size_t)sh * MAXP + pp) * GRP + g;
        float m  = act ? g_pm[idx] : -1e30f;
        float M = m;
        #pragma unroll
        for (int o = 4; o < 32; o <<= 1) M = fmaxf(M, __shfl_xor_sync(0xffffffffu, M, o));
        float w  = act ? exp2f((m - M) * LOG2E) : 0.f;
        float den = act ? w * g_ps[idx] : 0.f;
        #pragma unroll
        for (int o = 4; o < 32; o <<= 1) den += __shfl_xor_sync(0xffffffffu, den, o);
        if (pp < MAXP) sh_w[pp][g] = w / den;
    }
    __syncthreads();

    // ---- final output (vectorized: 128 float4) ----
    if (tid < 128) {
        const int g = tid >> 5;                      // 32 float4 per head
        float4 acc = make_float4(0.f, 0.f, 0.f, 0.f);
        for (int pp = 0; pp < np; pp++) {
            const float wv = sh_w[pp][g];
            float4 v = ((const float4*)g_po)[((size_t)sh * MAXP + pp) * 128 + tid];
            acc.x += wv * v.x; acc.y += wv * v.y;
            acc.z += wv * v.z; acc.w += wv * v.w;
        }
        ((float4*)out)[(size_t)s * (NUM_HEADS * HEAD_SIZE / 4)
                       + h * (GRP * HEAD_SIZE / 4) + tid] = acc;
    }
}

extern "C" void kernel_launch(void* const* d_in, const int* in_sizes, int n_in,
                              void* d_out, int out_size)
{
    const float* query       = (const float*)d_in[0];
    const float* key         = (const float*)d_in[1];
    const float* value       = (const float*)d_in[2];
    const float* key_cache   = (const float*)d_in[3];
    const float* value_cache = (const float*)d_in[4];
    const int*   block_tab   = (const int*)d_in[5];
    const int*   ctx_lens    = (const int*)d_in[6];
    float* out = (float*)d_out;

    paged_attn_split<<<NUM_SEQS * NUM_KV_HEADS * MAXP, 256>>>(
        query, key, value, key_cache, value_cache, block_tab, ctx_lens, out);
}